// round 14
// baseline (speedup 1.0000x reference)
#include <cuda_runtime.h>
#include <cuda_fp16.h>

#define NN 100000
#define EE 1600000
#define SCANB 391          // ceil(NN/256)

typedef unsigned long long u64;
typedef unsigned int u32;

// ---- scratch (__device__ globals; no allocations allowed) ----
__device__ __half   g_xlh[NN * 64];   // fp16 x @ Wl + bl
__device__ __half   g_xrh[NN * 64];   // fp16 x @ Wr + br
__device__ __half   g_Wt[96 * 16];    // transposed fp16 [We | Wg1]
__device__ float4   g_a4[EE];         // per-edge exp(alpha) per head
__device__ float    g_gate[EE];       // per-edge gate
__device__ int2     g_sed[EE];        // CSR-grouped {src, eid}
__device__ int      g_cnt[NN];
__device__ int      g_loc[NN];
__device__ int      g_bsum[512];
__device__ int      g_boff[512];
__device__ int      g_off[NN + 1];
__device__ int      g_cur[NN];

__device__ __forceinline__ float sigmoidf_(float v) {
    return 1.f / (1.f + __expf(-v));
}
__device__ __forceinline__ u64 pack2(float lo, float hi) {
    u64 r; asm("mov.b64 %0, {%1,%2};" : "=l"(r) : "f"(lo), "f"(hi)); return r;
}
__device__ __forceinline__ void unpack2(u64 v, float& lo, float& hi) {
    asm("mov.b64 {%0,%1}, %2;" : "=f"(lo), "=f"(hi) : "l"(v));
}
__device__ __forceinline__ void fma2(u64& d, u64 a, u64 b) {
    asm("fma.rn.f32x2 %0, %1, %2, %0;" : "+l"(d) : "l"(a), "l"(b));
}
__device__ __forceinline__ float leaky(float m) { return fmaxf(m, 0.2f * m); }
__device__ __forceinline__ void cpa16(__half* smem_dst, const __half* gsrc) {
    unsigned d = (unsigned)__cvta_generic_to_shared(smem_dst);
    asm volatile("cp.async.ca.shared.global [%0], [%1], 16;"
                 :: "r"(d), "l"(gsrc) : "memory");
}
__device__ __forceinline__ unsigned h2_bits(__half2 v) {
    return *reinterpret_cast<unsigned*>(&v);
}
__device__ __forceinline__ void mma16816(float& d0, float& d1, float& d2, float& d3,
                                         u32 a0, u32 a1, u32 a2, u32 a3,
                                         u32 b0, u32 b1) {
    asm volatile(
        "mma.sync.aligned.m16n8k16.row.col.f32.f16.f16.f32 "
        "{%0,%1,%2,%3}, {%4,%5,%6,%7}, {%8,%9}, {%0,%1,%2,%3};"
        : "+f"(d0), "+f"(d1), "+f"(d2), "+f"(d3)
        : "r"(a0), "r"(a1), "r"(a2), "r"(a3), "r"(b0), "r"(b1));
}

// ---------------------------------------------------------------------------
// Kernel 0: build transposed fp16 weight matrix Wt[96][16] = [We | Wg1]^T
// ---------------------------------------------------------------------------
__global__ void k_wcvt(const float* __restrict__ We, const float* __restrict__ Wg1) {
    int i = blockIdx.x * blockDim.x + threadIdx.x;
    if (i < 96 * 16) {
        int c = i >> 4, k = i & 15;
        float v = (c < 64) ? We[k * 64 + c] : Wg1[k * 32 + (c - 64)];
        g_Wt[i] = __float2half_rn(v);
    }
}

// ---------------------------------------------------------------------------
// Kernel 1: node transforms (fp16 out) + zero degree histogram.
// ---------------------------------------------------------------------------
__global__ void __launch_bounds__(256) k_prep(
        const float* __restrict__ x,
        const float* __restrict__ Wl, const float* __restrict__ bl,
        const float* __restrict__ Wr, const float* __restrict__ br) {
    __shared__ __align__(16) float Ws[64 * 128];
    __shared__ __align__(16) float xs[64 * 64];
    int t = threadIdx.x;
    int nb = blockIdx.x * 64;

#pragma unroll
    for (int i = 0; i < 16; i++) {
        int idx = t + i * 256;
        int k = idx >> 6, c = idx & 63;
        Ws[k * 128 + c]      = Wl[idx];
        Ws[k * 128 + 64 + c] = Wr[idx];
    }
#pragma unroll
    for (int i = 0; i < 16; i++) {
        int idx = t + i * 256;
        int n = nb + (idx >> 6);
        xs[idx] = (n < NN) ? x[(size_t)n * 64 + (idx & 63)] : 0.f;
    }
    if (t < 64 && nb + t < NN) g_cnt[nb + t] = 0;
    __syncthreads();

    int cg = t & 31, ng = t >> 5;
    int c0 = cg * 4;
    const float* bsrc = (c0 < 64) ? (bl + c0) : (br + (c0 - 64));
    float4 bias = *(const float4*)bsrc;

    u64 acc[8][2];
#pragma unroll
    for (int j = 0; j < 8; j++) {
        acc[j][0] = pack2(bias.x, bias.y);
        acc[j][1] = pack2(bias.z, bias.w);
    }

    for (int k4 = 0; k4 < 16; k4++) {
        float4 xv[8];
#pragma unroll
        for (int j = 0; j < 8; j++)
            xv[j] = *(const float4*)&xs[(ng * 8 + j) * 64 + k4 * 4];
#pragma unroll
        for (int kk = 0; kk < 4; kk++) {
            float4 wv = *(const float4*)&Ws[(k4 * 4 + kk) * 128 + c0];
            u64 w01 = pack2(wv.x, wv.y), w23 = pack2(wv.z, wv.w);
#pragma unroll
            for (int j = 0; j < 8; j++) {
                float xsc = (kk == 0) ? xv[j].x : (kk == 1) ? xv[j].y
                          : (kk == 2) ? xv[j].z : xv[j].w;
                u64 xx = pack2(xsc, xsc);
                fma2(acc[j][0], xx, w01);
                fma2(acc[j][1], xx, w23);
            }
        }
    }

    __half* dsth = (c0 < 64) ? g_xlh : g_xrh;
    int cc = c0 & 63;
#pragma unroll
    for (int j = 0; j < 8; j++) {
        int n = nb + ng * 8 + j;
        if (n < NN) {
            float o0, o1, o2, o3;
            unpack2(acc[j][0], o0, o1);
            unpack2(acc[j][1], o2, o3);
            uint2 p;
            p.x = h2_bits(__floats2half2_rn(o0, o1));
            p.y = h2_bits(__floats2half2_rn(o2, o3));
            *(uint2*)&dsth[(size_t)n * 64 + cc] = p;
        }
    }
}

// ---------------------------------------------------------------------------
// CSR construction (round-10 kernels, measured ~25us total)
// ---------------------------------------------------------------------------
__global__ void k_hist(const int* __restrict__ ei) {
    int e = blockIdx.x * blockDim.x + threadIdx.x;
    atomicAdd(&g_cnt[ei[EE + e]], 1);
}

__global__ void k_scanA() {
    __shared__ int s[256];
    int t = threadIdx.x;
    int n = blockIdx.x * 256 + t;
    int v = (n < NN) ? g_cnt[n] : 0;
    s[t] = v;
    __syncthreads();
#pragma unroll
    for (int o = 1; o < 256; o <<= 1) {
        int u = (t >= o) ? s[t - o] : 0;
        __syncthreads();
        s[t] += u;
        __syncthreads();
    }
    if (n < NN) g_loc[n] = s[t] - v;
    if (t == 255) g_bsum[blockIdx.x] = s[255];
}

__global__ void k_scanB() {
    __shared__ int s[512];
    int t = threadIdx.x;
    int v = (t < SCANB) ? g_bsum[t] : 0;
    s[t] = v;
    __syncthreads();
#pragma unroll
    for (int o = 1; o < 512; o <<= 1) {
        int u = (t >= o) ? s[t - o] : 0;
        __syncthreads();
        s[t] += u;
        __syncthreads();
    }
    g_boff[t] = s[t] - v;
}

__global__ void k_scanC() {
    int n = blockIdx.x * 256 + threadIdx.x;
    if (n < NN) {
        int o = g_loc[n] + g_boff[blockIdx.x];
        g_off[n] = o;
        g_cur[n] = o;
    }
    if (n == 0) g_off[NN] = EE;
}

__global__ void k_scatter(const int* __restrict__ ei) {
    int e = blockIdx.x * blockDim.x + threadIdx.x;
    int src = ei[e];
    int tgt = ei[EE + e];
    int p = atomicAdd(&g_cur[tgt], 1);
    g_sed[p] = make_int2(src, e);
}

// ---------------------------------------------------------------------------
// Kernel 2 (edge pass, tensor-core matmuls, ZERO atomics / ZERO scatter):
//   C[32,96] = ea[32,16] @ [We|Wg1] via 24x mma.sync.m16n8k16; epilogue adds
//   xl+xr, leaky, att-dot, SiLU gate, exp; stores a4 + gate coalesced.
// ---------------------------------------------------------------------------
#define ETPB 128
#define RST 72
#define EAST 20

__global__ void __launch_bounds__(ETPB) k_edge(
        const int* __restrict__ ei, const float* __restrict__ eag,
        const float* __restrict__ att, const float* __restrict__ Wg2,
        const float* __restrict__ bg1, const float* __restrict__ bg2p) {
    __shared__ __align__(16) __half sXL[4][32 * RST];
    __shared__ __align__(16) __half sXR[4][32 * RST];
    __shared__ __align__(16) __half sEA[4][32 * EAST];
    __shared__ __align__(16) __half sWt[96 * 16];
    __shared__ __align__(16) float  sAtt[64];
    __shared__ __align__(8)  float  sWg2[32];
    __shared__ __align__(8)  float  sBg1[32];

    int t = threadIdx.x, lane = t & 31, w = t >> 5;
    __half* XL = sXL[w];
    __half* XR = sXR[w];
    __half* EA = sEA[w];

    for (int i = t; i < 192; i += ETPB)
        cpa16(&sWt[i * 8], &g_Wt[i * 8]);
    if (t < 64) sAtt[t] = att[t];
    if (t >= 64 && t < 96)  sWg2[t - 64] = Wg2[t - 64];
    if (t >= 96 && t < 128) sBg1[t - 96] = bg1[t - 96];

    int e = blockIdx.x * ETPB + t;
    int src = ei[e];
    int tgt = ei[EE + e];
    (void)tgt;

    int rlane = lane >> 3;
    int off8  = (lane & 7) * 8;
#pragma unroll
    for (int i = 0; i < 8; i++) {
        int r  = i * 4 + rlane;
        int s  = __shfl_sync(0xFFFFFFFFu, src, r);
        int tg = __shfl_sync(0xFFFFFFFFu, tgt, r);
        cpa16(&XL[r * RST + off8], g_xlh + (size_t)s  * 64 + off8);
        cpa16(&XR[r * RST + off8], g_xrh + (size_t)tg * 64 + off8);
    }
    asm volatile("cp.async.commit_group;" ::: "memory");

    // coalesced eag load + fp16 transpose into EA[32][20]
    {
        const float4* eabase = (const float4*)eag
                             + (size_t)(blockIdx.x * ETPB + 32 * w) * 4;
#pragma unroll
        for (int i = 0; i < 4; i++) {
            int j = lane + 32 * i;
            float4 v = eabase[j];
            int ed = j >> 2, qq = j & 3;
            uint2 p;
            p.x = h2_bits(__floats2half2_rn(v.x, v.y));
            p.y = h2_bits(__floats2half2_rn(v.z, v.w));
            *(uint2*)&EA[ed * EAST + qq * 4] = p;
        }
    }
    float bg2v = bg2p[0];

    asm volatile("cp.async.wait_group 0;" ::: "memory");
    __syncthreads();

    int gr = lane >> 2;
    int q  = lane & 3;

    u32 a0m0 = *(const u32*)&EA[gr * EAST + 2 * q];
    u32 a1m0 = *(const u32*)&EA[(gr + 8) * EAST + 2 * q];
    u32 a2m0 = *(const u32*)&EA[gr * EAST + 2 * q + 8];
    u32 a3m0 = *(const u32*)&EA[(gr + 8) * EAST + 2 * q + 8];
    u32 a0m1 = *(const u32*)&EA[(gr + 16) * EAST + 2 * q];
    u32 a1m1 = *(const u32*)&EA[(gr + 24) * EAST + 2 * q];
    u32 a2m1 = *(const u32*)&EA[(gr + 16) * EAST + 2 * q + 8];
    u32 a3m1 = *(const u32*)&EA[(gr + 24) * EAST + 2 * q + 8];

    float ap[4][4] = {};
    float gp[4]    = {0.f, 0.f, 0.f, 0.f};

#pragma unroll
    for (int nt = 0; nt < 12; nt++) {
        u32 b0 = *(const u32*)&sWt[(8 * nt + gr) * 16 + 2 * q];
        u32 b1 = *(const u32*)&sWt[(8 * nt + gr) * 16 + 2 * q + 8];

#pragma unroll
        for (int mt = 0; mt < 2; mt++) {
            float d0 = 0.f, d1 = 0.f, d2 = 0.f, d3 = 0.f;
            if (mt == 0) mma16816(d0, d1, d2, d3, a0m0, a1m0, a2m0, a3m0, b0, b1);
            else         mma16816(d0, d1, d2, d3, a0m1, a1m1, a2m1, a3m1, b0, b1);

            int r0 = gr + 16 * mt;
            if (nt < 8) {
                int col = 8 * nt + 2 * q;
                int h   = nt >> 1;
                float2 attv = *(const float2*)&sAtt[col];
                __half2 xl2 = *(const __half2*)&XL[r0 * RST + col];
                __half2 xr2 = *(const __half2*)&XR[r0 * RST + col];
                float2 f = __half22float2(__hadd2(xl2, xr2));
                float m0 = d0 + f.x, m1 = d1 + f.y;
                ap[2 * mt][h] += leaky(m0) * attv.x + leaky(m1) * attv.y;
                xl2 = *(const __half2*)&XL[(r0 + 8) * RST + col];
                xr2 = *(const __half2*)&XR[(r0 + 8) * RST + col];
                f = __half22float2(__hadd2(xl2, xr2));
                m0 = d2 + f.x; m1 = d3 + f.y;
                ap[2 * mt + 1][h] += leaky(m0) * attv.x + leaky(m1) * attv.y;
            } else {
                int hc = 8 * (nt - 8) + 2 * q;
                float2 b1v = *(const float2*)&sBg1[hc];
                float2 w2v = *(const float2*)&sWg2[hc];
                float h0 = d0 + b1v.x, h1 = d1 + b1v.y;
                gp[2 * mt]     += h0 * sigmoidf_(h0) * w2v.x +
                                  h1 * sigmoidf_(h1) * w2v.y;
                h0 = d2 + b1v.x; h1 = d3 + b1v.y;
                gp[2 * mt + 1] += h0 * sigmoidf_(h0) * w2v.x +
                                  h1 * sigmoidf_(h1) * w2v.y;
            }
        }
    }

#pragma unroll
    for (int s = 0; s < 4; s++) {
#pragma unroll
        for (int h = 0; h < 4; h++) {
            ap[s][h] += __shfl_xor_sync(0xFFFFFFFFu, ap[s][h], 1);
            ap[s][h] += __shfl_xor_sync(0xFFFFFFFFu, ap[s][h], 2);
        }
        gp[s] += __shfl_xor_sync(0xFFFFFFFFu, gp[s], 1);
        gp[s] += __shfl_xor_sync(0xFFFFFFFFu, gp[s], 2);
    }

    // lane q of each quad finalizes row r = gr + 8q  (all 32 rows covered)
    int r = gr + 8 * q;
    int ebase = blockIdx.x * ETPB + 32 * w;
    float4 a4 = make_float4(__expf(ap[q][0]), __expf(ap[q][1]),
                            __expf(ap[q][2]), __expf(ap[q][3]));
    g_a4[ebase + r]   = a4;
    g_gate[ebase + r] = sigmoidf_(gp[q] + bg2v);
}

// ---------------------------------------------------------------------------
// Kernel 3: per-node gather (batched x4) + softmax-normalize + gate-mean +
// LayerNorm + SiLU + residual. One warp per node, zero atomics.
// ---------------------------------------------------------------------------
__global__ void __launch_bounds__(256) k_gather(
        const float* __restrict__ x,
        const float* __restrict__ conv_bias,
        const float* __restrict__ gamma,
        const float* __restrict__ beta,
        float* __restrict__ out) {
    int n = (blockIdx.x * blockDim.x + threadIdx.x) >> 5;
    int lane = threadIdx.x & 31;
    int h = lane >> 3;

    int row = g_off[n];
    int deg = g_off[n + 1] - row;

    u64 acc = pack2(0.f, 0.f);
    float den = 0.f, gsum = 0.f;

    for (int j0 = 0; j0 < deg; j0 += 4) {
        int km = deg - j0;
        int2 se0 = g_sed[row + j0];
        int2 se1 = g_sed[row + j0 + ((km > 1) ? 1 : 0)];
        int2 se2 = g_sed[row + j0 + ((km > 2) ? 2 : 0)];
        int2 se3 = g_sed[row + j0 + ((km > 3) ? 3 : 0)];

        float4 a40 = g_a4[se0.y], a41 = g_a4[se1.y],
               a42 = g_a4[se2.y], a43 = g_a4[se3.y];
        float  gt0 = g_gate[se0.y], gt1 = g_gate[se1.y],
               gt2 = g_gate[se2.y], gt3 = g_gate[se3.y];
        __half2 x0 = *(const __half2*)&g_xlh[(size_t)se0.x * 64 + 2 * lane];
        __half2 x1 = *(const __half2*)&g_xlh[(size_t)se1.x * 64 + 2 * lane];
        __half2 x2 = *(const __half2*)&g_xlh[(size_t)se2.x * 64 + 2 * lane];
        __half2 x3 = *(const __half2*)&g_xlh[(size_t)se3.x * 64 + 2 * lane];

        float m1 = (km > 1) ? 1.f : 0.f;
        float m2 = (km > 2) ? 1.f : 0.f;
        float m3 = (km > 3) ? 1.f : 0.f;

        float a0 = (h == 0) ? a40.x : (h == 1) ? a40.y : (h == 2) ? a40.z : a40.w;
        float a1 = ((h == 0) ? a41.x : (h == 1) ? a41.y : (h == 2) ? a41.z : a41.w) * m1;
        float a2 = ((h == 0) ? a42.x : (h == 1) ? a42.y : (h == 2) ? a42.z : a42.w) * m2;
        float a3 = ((h == 0) ? a43.x : (h == 1) ? a43.y : (h == 2) ? a43.z : a43.w) * m3;

        float2 f0 = __half22float2(x0), f1 = __half22float2(x1);
        float2 f2 = __half22float2(x2), f3 = __half22float2(x3);
        fma2(acc, pack2(a0, a0), pack2(f0.x, f0.y));
        fma2(acc, pack2(a1, a1), pack2(f1.x, f1.y));
        fma2(acc, pack2(a2, a2), pack2(f2.x, f2.y));
        fma2(acc, pack2(a3, a3), pack2(f3.x, f3.y));
        den  += (a0 + a1) + (a2 + a3);
        gsum += gt0 + gt1 * m1 + gt2 * m2 + gt3 * m3;
    }

    float inv = den > 0.f ? 1.f / den : 0.f;
    float mg  = gsum / fmaxf((float)deg, 1.f);

    float2 cb = ((const float2*)conv_bias)[lane];
    float a0, a1; unpack2(acc, a0, a1);
    float v0 = (a0 * inv + cb.x) * mg;
    float v1 = (a1 * inv + cb.y) * mg;

    float s  = v0 + v1;
    float sq = v0 * v0 + v1 * v1;
#pragma unroll
    for (int o = 16; o > 0; o >>= 1) {
        s  += __shfl_xor_sync(0xFFFFFFFFu, s,  o);
        sq += __shfl_xor_sync(0xFFFFFFFFu, sq, o);
    }
    float mu   = s * (1.f / 64.f);
    float var  = sq * (1.f / 64.f) - mu * mu;
    float rstd = rsqrtf(var + 1e-5f);

    float2 g  = ((const float2*)gamma)[lane];
    float2 bt = ((const float2*)beta)[lane];
    float2 xv = ((const float2*)x)[(size_t)n * 32 + lane];
    float n0 = (v0 - mu) * rstd * g.x + bt.x;
    float n1 = (v1 - mu) * rstd * g.y + bt.y;
    n0 *= sigmoidf_(n0);
    n1 *= sigmoidf_(n1);
    ((float2*)out)[(size_t)n * 32 + lane] = make_float2(n0 + xv.x, n1 + xv.y);
}

// ---------------------------------------------------------------------------
extern "C" void kernel_launch(void* const* d_in, const int* in_sizes, int n_in,
                              void* d_out, int out_size) {
    const float* x         = (const float*)d_in[0];
    const int*   ei        = (const int*)  d_in[1];
    const float* edge_attr = (const float*)d_in[2];
    const float* Wl        = (const float*)d_in[3];
    const float* bl        = (const float*)d_in[4];
    const float* Wr        = (const float*)d_in[5];
    const float* br        = (const float*)d_in[6];
    const float* We        = (const float*)d_in[7];
    const float* att       = (const float*)d_in[8];
    const float* conv_bias = (const float*)d_in[9];
    const float* Wg1       = (const float*)d_in[10];
    const float* bg1       = (const float*)d_in[11];
    const float* Wg2       = (const float*)d_in[12];
    const float* bg2       = (const float*)d_in[13];
    const float* gamma     = (const float*)d_in[14];
    const float* beta      = (const float*)d_in[15];
    float* out = (float*)d_out;

    k_wcvt   <<<6, 256>>>(We, Wg1);
    k_prep   <<<(NN + 63) / 64, 256>>>(x, Wl, bl, Wr, br);
    k_hist   <<<EE / 256, 256>>>(ei);
    k_scanA  <<<SCANB, 256>>>();
    k_scanB  <<<1, 512>>>();
    k_scanC  <<<SCANB, 256>>>();
    k_scatter<<<EE / 256, 256>>>(ei);
    k_edge   <<<EE / ETPB, ETPB>>>(ei, edge_attr, att, Wg2, bg1, bg2);
    k_gather <<<NN * 32 / 256, 256>>>(x, conv_bias, gamma, beta, out);
}

// round 15
// speedup vs baseline: 1.0015x; 1.0015x over previous
#include <cuda_runtime.h>
#include <cuda_fp16.h>

#define NN 100000
#define EE 1600000
#define SCANB 391          // ceil(NN/256)

typedef unsigned long long u64;
typedef unsigned int u32;

// ---- scratch (__device__ globals; no allocations allowed) ----
__device__ __half   g_xlh[NN * 64];   // fp16 x @ Wl + bl
__device__ __half   g_xrh[NN * 64];   // fp16 x @ Wr + br
__device__ __half   g_Wt[96 * 16];    // transposed fp16 [We | Wg1]
__device__ float4   g_a4p[EE];        // exp(alpha) per head, CSR-PERMUTED
__device__ float    g_gatep[EE];      // gate, CSR-PERMUTED
__device__ int      g_srcp[EE];       // src node id, CSR-PERMUTED
__device__ int      g_pos[EE];        // eid -> CSR position
__device__ int      g_cnt[NN];
__device__ int      g_loc[NN];
__device__ int      g_bsum[512];
__device__ int      g_boff[512];
__device__ int      g_off[NN + 1];
__device__ int      g_cur[NN];

__device__ __forceinline__ float sigmoidf_(float v) {
    return 1.f / (1.f + __expf(-v));
}
__device__ __forceinline__ u64 pack2(float lo, float hi) {
    u64 r; asm("mov.b64 %0, {%1,%2};" : "=l"(r) : "f"(lo), "f"(hi)); return r;
}
__device__ __forceinline__ void unpack2(u64 v, float& lo, float& hi) {
    asm("mov.b64 {%0,%1}, %2;" : "=f"(lo), "=f"(hi) : "l"(v));
}
__device__ __forceinline__ void fma2(u64& d, u64 a, u64 b) {
    asm("fma.rn.f32x2 %0, %1, %2, %0;" : "+l"(d) : "l"(a), "l"(b));
}
__device__ __forceinline__ float leaky(float m) { return fmaxf(m, 0.2f * m); }
__device__ __forceinline__ void cpa16(__half* smem_dst, const __half* gsrc) {
    unsigned d = (unsigned)__cvta_generic_to_shared(smem_dst);
    asm volatile("cp.async.ca.shared.global [%0], [%1], 16;"
                 :: "r"(d), "l"(gsrc) : "memory");
}
__device__ __forceinline__ unsigned h2_bits(__half2 v) {
    return *reinterpret_cast<unsigned*>(&v);
}
__device__ __forceinline__ void mma16816(float& d0, float& d1, float& d2, float& d3,
                                         u32 a0, u32 a1, u32 a2, u32 a3,
                                         u32 b0, u32 b1) {
    asm volatile(
        "mma.sync.aligned.m16n8k16.row.col.f32.f16.f16.f32 "
        "{%0,%1,%2,%3}, {%4,%5,%6,%7}, {%8,%9}, {%0,%1,%2,%3};"
        : "+f"(d0), "+f"(d1), "+f"(d2), "+f"(d3)
        : "r"(a0), "r"(a1), "r"(a2), "r"(a3), "r"(b0), "r"(b1));
}

// ---------------------------------------------------------------------------
// Kernel 0: build transposed fp16 weight matrix Wt[96][16] = [We | Wg1]^T
// ---------------------------------------------------------------------------
__global__ void k_wcvt(const float* __restrict__ We, const float* __restrict__ Wg1) {
    int i = blockIdx.x * blockDim.x + threadIdx.x;
    if (i < 96 * 16) {
        int c = i >> 4, k = i & 15;
        float v = (c < 64) ? We[k * 64 + c] : Wg1[k * 32 + (c - 64)];
        g_Wt[i] = __float2half_rn(v);
    }
}

// ---------------------------------------------------------------------------
// Kernel 1: node transforms (fp16 out) + zero degree histogram.
// ---------------------------------------------------------------------------
__global__ void __launch_bounds__(256) k_prep(
        const float* __restrict__ x,
        const float* __restrict__ Wl, const float* __restrict__ bl,
        const float* __restrict__ Wr, const float* __restrict__ br) {
    __shared__ __align__(16) float Ws[64 * 128];
    __shared__ __align__(16) float xs[64 * 64];
    int t = threadIdx.x;
    int nb = blockIdx.x * 64;

#pragma unroll
    for (int i = 0; i < 16; i++) {
        int idx = t + i * 256;
        int k = idx >> 6, c = idx & 63;
        Ws[k * 128 + c]      = Wl[idx];
        Ws[k * 128 + 64 + c] = Wr[idx];
    }
#pragma unroll
    for (int i = 0; i < 16; i++) {
        int idx = t + i * 256;
        int n = nb + (idx >> 6);
        xs[idx] = (n < NN) ? x[(size_t)n * 64 + (idx & 63)] : 0.f;
    }
    if (t < 64 && nb + t < NN) g_cnt[nb + t] = 0;
    __syncthreads();

    int cg = t & 31, ng = t >> 5;
    int c0 = cg * 4;
    const float* bsrc = (c0 < 64) ? (bl + c0) : (br + (c0 - 64));
    float4 bias = *(const float4*)bsrc;

    u64 acc[8][2];
#pragma unroll
    for (int j = 0; j < 8; j++) {
        acc[j][0] = pack2(bias.x, bias.y);
        acc[j][1] = pack2(bias.z, bias.w);
    }

    for (int k4 = 0; k4 < 16; k4++) {
        float4 xv[8];
#pragma unroll
        for (int j = 0; j < 8; j++)
            xv[j] = *(const float4*)&xs[(ng * 8 + j) * 64 + k4 * 4];
#pragma unroll
        for (int kk = 0; kk < 4; kk++) {
            float4 wv = *(const float4*)&Ws[(k4 * 4 + kk) * 128 + c0];
            u64 w01 = pack2(wv.x, wv.y), w23 = pack2(wv.z, wv.w);
#pragma unroll
            for (int j = 0; j < 8; j++) {
                float xsc = (kk == 0) ? xv[j].x : (kk == 1) ? xv[j].y
                          : (kk == 2) ? xv[j].z : xv[j].w;
                u64 xx = pack2(xsc, xsc);
                fma2(acc[j][0], xx, w01);
                fma2(acc[j][1], xx, w23);
            }
        }
    }

    __half* dsth = (c0 < 64) ? g_xlh : g_xrh;
    int cc = c0 & 63;
#pragma unroll
    for (int j = 0; j < 8; j++) {
        int n = nb + ng * 8 + j;
        if (n < NN) {
            float o0, o1, o2, o3;
            unpack2(acc[j][0], o0, o1);
            unpack2(acc[j][1], o2, o3);
            uint2 p;
            p.x = h2_bits(__floats2half2_rn(o0, o1));
            p.y = h2_bits(__floats2half2_rn(o2, o3));
            *(uint2*)&dsth[(size_t)n * 64 + cc] = p;
        }
    }
}

// ---------------------------------------------------------------------------
// CSR construction: histogram -> scan -> scatter (+ permutation g_pos)
// ---------------------------------------------------------------------------
__global__ void k_hist(const int* __restrict__ ei) {
    int e = blockIdx.x * blockDim.x + threadIdx.x;
    atomicAdd(&g_cnt[ei[EE + e]], 1);
}

__global__ void k_scanA() {
    __shared__ int s[256];
    int t = threadIdx.x;
    int n = blockIdx.x * 256 + t;
    int v = (n < NN) ? g_cnt[n] : 0;
    s[t] = v;
    __syncthreads();
#pragma unroll
    for (int o = 1; o < 256; o <<= 1) {
        int u = (t >= o) ? s[t - o] : 0;
        __syncthreads();
        s[t] += u;
        __syncthreads();
    }
    if (n < NN) g_loc[n] = s[t] - v;
    if (t == 255) g_bsum[blockIdx.x] = s[255];
}

__global__ void k_scanB() {
    __shared__ int s[512];
    int t = threadIdx.x;
    int v = (t < SCANB) ? g_bsum[t] : 0;
    s[t] = v;
    __syncthreads();
#pragma unroll
    for (int o = 1; o < 512; o <<= 1) {
        int u = (t >= o) ? s[t - o] : 0;
        __syncthreads();
        s[t] += u;
        __syncthreads();
    }
    g_boff[t] = s[t] - v;
}

__global__ void k_scanC() {
    int n = blockIdx.x * 256 + threadIdx.x;
    if (n < NN) {
        int o = g_loc[n] + g_boff[blockIdx.x];
        g_off[n] = o;
        g_cur[n] = o;
    }
    if (n == 0) g_off[NN] = EE;
}

__global__ void k_scatter(const int* __restrict__ ei) {
    int e = blockIdx.x * blockDim.x + threadIdx.x;
    int src = ei[e];
    int tgt = ei[EE + e];
    int p = atomicAdd(&g_cur[tgt], 1);
    g_srcp[p] = src;
    g_pos[e]  = p;
}

// ---------------------------------------------------------------------------
// Kernel 2 (edge pass, tensor-core matmuls, no atomics):
//   stores a4 + gate DIRECTLY INTO CSR ORDER via g_pos (scattered STG).
// ---------------------------------------------------------------------------
#define ETPB 128
#define RST 72
#define EAST 20

__global__ void __launch_bounds__(ETPB) k_edge(
        const int* __restrict__ ei, const float* __restrict__ eag,
        const float* __restrict__ att, const float* __restrict__ Wg2,
        const float* __restrict__ bg1, const float* __restrict__ bg2p) {
    __shared__ __align__(16) __half sXL[4][32 * RST];
    __shared__ __align__(16) __half sXR[4][32 * RST];
    __shared__ __align__(16) __half sEA[4][32 * EAST];
    __shared__ __align__(16) __half sWt[96 * 16];
    __shared__ __align__(16) float  sAtt[64];
    __shared__ __align__(8)  float  sWg2[32];
    __shared__ __align__(8)  float  sBg1[32];

    int t = threadIdx.x, lane = t & 31, w = t >> 5;
    __half* XL = sXL[w];
    __half* XR = sXR[w];
    __half* EA = sEA[w];

    for (int i = t; i < 192; i += ETPB)
        cpa16(&sWt[i * 8], &g_Wt[i * 8]);
    if (t < 64) sAtt[t] = att[t];
    if (t >= 64 && t < 96)  sWg2[t - 64] = Wg2[t - 64];
    if (t >= 96 && t < 128) sBg1[t - 96] = bg1[t - 96];

    int e = blockIdx.x * ETPB + t;
    int src = ei[e];
    int tgt = ei[EE + e];

    int rlane = lane >> 3;
    int off8  = (lane & 7) * 8;
#pragma unroll
    for (int i = 0; i < 8; i++) {
        int r  = i * 4 + rlane;
        int s  = __shfl_sync(0xFFFFFFFFu, src, r);
        int tg = __shfl_sync(0xFFFFFFFFu, tgt, r);
        cpa16(&XL[r * RST + off8], g_xlh + (size_t)s  * 64 + off8);
        cpa16(&XR[r * RST + off8], g_xrh + (size_t)tg * 64 + off8);
    }
    asm volatile("cp.async.commit_group;" ::: "memory");

    // coalesced eag load + fp16 transpose into EA[32][20]
    {
        const float4* eabase = (const float4*)eag
                             + (size_t)(blockIdx.x * ETPB + 32 * w) * 4;
#pragma unroll
        for (int i = 0; i < 4; i++) {
            int j = lane + 32 * i;
            float4 v = eabase[j];
            int ed = j >> 2, qq = j & 3;
            uint2 p;
            p.x = h2_bits(__floats2half2_rn(v.x, v.y));
            p.y = h2_bits(__floats2half2_rn(v.z, v.w));
            *(uint2*)&EA[ed * EAST + qq * 4] = p;
        }
    }
    float bg2v = bg2p[0];

    asm volatile("cp.async.wait_group 0;" ::: "memory");
    __syncthreads();

    int gr = lane >> 2;
    int q  = lane & 3;

    u32 a0m0 = *(const u32*)&EA[gr * EAST + 2 * q];
    u32 a1m0 = *(const u32*)&EA[(gr + 8) * EAST + 2 * q];
    u32 a2m0 = *(const u32*)&EA[gr * EAST + 2 * q + 8];
    u32 a3m0 = *(const u32*)&EA[(gr + 8) * EAST + 2 * q + 8];
    u32 a0m1 = *(const u32*)&EA[(gr + 16) * EAST + 2 * q];
    u32 a1m1 = *(const u32*)&EA[(gr + 24) * EAST + 2 * q];
    u32 a2m1 = *(const u32*)&EA[(gr + 16) * EAST + 2 * q + 8];
    u32 a3m1 = *(const u32*)&EA[(gr + 24) * EAST + 2 * q + 8];

    float ap[4][4] = {};
    float gp[4]    = {0.f, 0.f, 0.f, 0.f};

#pragma unroll
    for (int nt = 0; nt < 12; nt++) {
        u32 b0 = *(const u32*)&sWt[(8 * nt + gr) * 16 + 2 * q];
        u32 b1 = *(const u32*)&sWt[(8 * nt + gr) * 16 + 2 * q + 8];

#pragma unroll
        for (int mt = 0; mt < 2; mt++) {
            float d0 = 0.f, d1 = 0.f, d2 = 0.f, d3 = 0.f;
            if (mt == 0) mma16816(d0, d1, d2, d3, a0m0, a1m0, a2m0, a3m0, b0, b1);
            else         mma16816(d0, d1, d2, d3, a0m1, a1m1, a2m1, a3m1, b0, b1);

            int r0 = gr + 16 * mt;
            if (nt < 8) {
                int col = 8 * nt + 2 * q;
                int h   = nt >> 1;
                float2 attv = *(const float2*)&sAtt[col];
                __half2 xl2 = *(const __half2*)&XL[r0 * RST + col];
                __half2 xr2 = *(const __half2*)&XR[r0 * RST + col];
                float2 f = __half22float2(__hadd2(xl2, xr2));
                float m0 = d0 + f.x, m1 = d1 + f.y;
                ap[2 * mt][h] += leaky(m0) * attv.x + leaky(m1) * attv.y;
                xl2 = *(const __half2*)&XL[(r0 + 8) * RST + col];
                xr2 = *(const __half2*)&XR[(r0 + 8) * RST + col];
                f = __half22float2(__hadd2(xl2, xr2));
                m0 = d2 + f.x; m1 = d3 + f.y;
                ap[2 * mt + 1][h] += leaky(m0) * attv.x + leaky(m1) * attv.y;
            } else {
                int hc = 8 * (nt - 8) + 2 * q;
                float2 b1v = *(const float2*)&sBg1[hc];
                float2 w2v = *(const float2*)&sWg2[hc];
                float h0 = d0 + b1v.x, h1 = d1 + b1v.y;
                gp[2 * mt]     += h0 * sigmoidf_(h0) * w2v.x +
                                  h1 * sigmoidf_(h1) * w2v.y;
                h0 = d2 + b1v.x; h1 = d3 + b1v.y;
                gp[2 * mt + 1] += h0 * sigmoidf_(h0) * w2v.x +
                                  h1 * sigmoidf_(h1) * w2v.y;
            }
        }
    }

#pragma unroll
    for (int s = 0; s < 4; s++) {
#pragma unroll
        for (int h = 0; h < 4; h++) {
            ap[s][h] += __shfl_xor_sync(0xFFFFFFFFu, ap[s][h], 1);
            ap[s][h] += __shfl_xor_sync(0xFFFFFFFFu, ap[s][h], 2);
        }
        gp[s] += __shfl_xor_sync(0xFFFFFFFFu, gp[s], 1);
        gp[s] += __shfl_xor_sync(0xFFFFFFFFu, gp[s], 2);
    }

    // lane q of each quad finalizes row r = gr + 8q; store into CSR order
    int r = gr + 8 * q;
    int ebase = blockIdx.x * ETPB + 32 * w;
    int p = g_pos[ebase + r];
    float4 a4 = make_float4(__expf(ap[q][0]), __expf(ap[q][1]),
                            __expf(ap[q][2]), __expf(ap[q][3]));
    g_a4p[p]   = a4;
    g_gatep[p] = sigmoidf_(gp[q] + bg2v);
}

// ---------------------------------------------------------------------------
// Kernel 3: per-node gather — ALL edge data read as coalesced CSR streams
// (src, a4, gate); only the xl rows are gathers (L2-resident, 1 wf each).
// One warp per node; softmax-normalize + gate-mean + LN + SiLU + residual.
// ---------------------------------------------------------------------------
__global__ void __launch_bounds__(256) k_gather(
        const float* __restrict__ x,
        const float* __restrict__ conv_bias,
        const float* __restrict__ gamma,
        const float* __restrict__ beta,
        float* __restrict__ out) {
    int n = (blockIdx.x * blockDim.x + threadIdx.x) >> 5;
    int lane = threadIdx.x & 31;
    int h = lane >> 3;

    int row = g_off[n];
    int deg = g_off[n + 1] - row;

    u64 acc = pack2(0.f, 0.f);
    float den = 0.f, gsum = 0.f;

    for (int j0 = 0; j0 < deg; j0 += 4) {
        int km = deg - j0;
        int i1 = row + j0 + ((km > 1) ? 1 : 0);
        int i2 = row + j0 + ((km > 2) ? 2 : 0);
        int i3 = row + j0 + ((km > 3) ? 3 : 0);

        int s0 = g_srcp[row + j0], s1 = g_srcp[i1],
            s2 = g_srcp[i2],       s3 = g_srcp[i3];
        float4 a40 = g_a4p[row + j0], a41 = g_a4p[i1],
               a42 = g_a4p[i2],       a43 = g_a4p[i3];
        float  gt0 = g_gatep[row + j0], gt1 = g_gatep[i1],
               gt2 = g_gatep[i2],       gt3 = g_gatep[i3];
        __half2 x0 = *(const __half2*)&g_xlh[(size_t)s0 * 64 + 2 * lane];
        __half2 x1 = *(const __half2*)&g_xlh[(size_t)s1 * 64 + 2 * lane];
        __half2 x2 = *(const __half2*)&g_xlh[(size_t)s2 * 64 + 2 * lane];
        __half2 x3 = *(const __half2*)&g_xlh[(size_t)s3 * 64 + 2 * lane];

        float m1 = (km > 1) ? 1.f : 0.f;
        float m2 = (km > 2) ? 1.f : 0.f;
        float m3 = (km > 3) ? 1.f : 0.f;

        float a0 = (h == 0) ? a40.x : (h == 1) ? a40.y : (h == 2) ? a40.z : a40.w;
        float a1 = ((h == 0) ? a41.x : (h == 1) ? a41.y : (h == 2) ? a41.z : a41.w) * m1;
        float a2 = ((h == 0) ? a42.x : (h == 1) ? a42.y : (h == 2) ? a42.z : a42.w) * m2;
        float a3 = ((h == 0) ? a43.x : (h == 1) ? a43.y : (h == 2) ? a43.z : a43.w) * m3;

        float2 f0 = __half22float2(x0), f1 = __half22float2(x1);
        float2 f2 = __half22float2(x2), f3 = __half22float2(x3);
        fma2(acc, pack2(a0, a0), pack2(f0.x, f0.y));
        fma2(acc, pack2(a1, a1), pack2(f1.x, f1.y));
        fma2(acc, pack2(a2, a2), pack2(f2.x, f2.y));
        fma2(acc, pack2(a3, a3), pack2(f3.x, f3.y));
        den  += (a0 + a1) + (a2 + a3);
        gsum += gt0 + gt1 * m1 + gt2 * m2 + gt3 * m3;
    }

    float inv = den > 0.f ? 1.f / den : 0.f;
    float mg  = gsum / fmaxf((float)deg, 1.f);

    float2 cb = ((const float2*)conv_bias)[lane];
    float a0, a1; unpack2(acc, a0, a1);
    float v0 = (a0 * inv + cb.x) * mg;
    float v1 = (a1 * inv + cb.y) * mg;

    float s  = v0 + v1;
    float sq = v0 * v0 + v1 * v1;
#pragma unroll
    for (int o = 16; o > 0; o >>= 1) {
        s  += __shfl_xor_sync(0xFFFFFFFFu, s,  o);
        sq += __shfl_xor_sync(0xFFFFFFFFu, sq, o);
    }
    float mu   = s * (1.f / 64.f);
    float var  = sq * (1.f / 64.f) - mu * mu;
    float rstd = rsqrtf(var + 1e-5f);

    float2 g  = ((const float2*)gamma)[lane];
    float2 bt = ((const float2*)beta)[lane];
    float2 xv = ((const float2*)x)[(size_t)n * 32 + lane];
    float n0 = (v0 - mu) * rstd * g.x + bt.x;
    float n1 = (v1 - mu) * rstd * g.y + bt.y;
    n0 *= sigmoidf_(n0);
    n1 *= sigmoidf_(n1);
    ((float2*)out)[(size_t)n * 32 + lane] = make_float2(n0 + xv.x, n1 + xv.y);
}

// ---------------------------------------------------------------------------
extern "C" void kernel_launch(void* const* d_in, const int* in_sizes, int n_in,
                              void* d_out, int out_size) {
    const float* x         = (const float*)d_in[0];
    const int*   ei        = (const int*)  d_in[1];
    const float* edge_attr = (const float*)d_in[2];
    const float* Wl        = (const float*)d_in[3];
    const float* bl        = (const float*)d_in[4];
    const float* Wr        = (const float*)d_in[5];
    const float* br        = (const float*)d_in[6];
    const float* We        = (const float*)d_in[7];
    const float* att       = (const float*)d_in[8];
    const float* conv_bias = (const float*)d_in[9];
    const float* Wg1       = (const float*)d_in[10];
    const float* bg1       = (const float*)d_in[11];
    const float* Wg2       = (const float*)d_in[12];
    const float* bg2       = (const float*)d_in[13];
    const float* gamma     = (const float*)d_in[14];
    const float* beta      = (const float*)d_in[15];
    float* out = (float*)d_out;

    k_wcvt   <<<6, 256>>>(We, Wg1);
    k_prep   <<<(NN + 63) / 64, 256>>>(x, Wl, bl, Wr, br);
    k_hist   <<<EE / 256, 256>>>(ei);
    k_scanA  <<<SCANB, 256>>>();
    k_scanB  <<<1, 512>>>();
    k_scanC  <<<SCANB, 256>>>();
    k_scatter<<<EE / 256, 256>>>(ei);
    k_edge   <<<EE / ETPB, ETPB>>>(ei, edge_attr, att, Wg2, bg1, bg2);
    k_gather <<<NN * 32 / 256, 256>>>(x, conv_bias, gamma, beta, out);
}

// round 16
// speedup vs baseline: 1.2703x; 1.2684x over previous
#include <cuda_runtime.h>
#include <cuda_fp16.h>

#define NN 100000
#define EE 1600000
#define TPB 256

typedef unsigned long long u64;
typedef unsigned int u32;

// ---- scratch (__device__ globals; no allocations allowed) ----
__device__ __half   g_xlh[NN * 64];   // fp16 x @ Wl + bl (logits + messages)
__device__ __half   g_xrh[NN * 64];   // fp16 x @ Wr + br (logits only)
__device__ float4   g_denom[NN];      // per-head softmax denominators
__device__ float2   g_gate2[NN];      // {gate_sum, degree} per target
__device__ __align__(16) __half g_Wt[96 * 16];   // fp16 [We | Wg1]^T

__device__ __forceinline__ float sigmoidf_(float v) {
    return 1.f / (1.f + __expf(-v));
}
__device__ __forceinline__ u64 pack2(float lo, float hi) {
    u64 r; asm("mov.b64 %0, {%1,%2};" : "=l"(r) : "f"(lo), "f"(hi)); return r;
}
__device__ __forceinline__ void unpack2(u64 v, float& lo, float& hi) {
    asm("mov.b64 {%0,%1}, %2;" : "=f"(lo), "=f"(hi) : "l"(v));
}
__device__ __forceinline__ void fma2(u64& d, u64 a, u64 b) {
    asm("fma.rn.f32x2 %0, %1, %2, %0;" : "+l"(d) : "l"(a), "l"(b));
}
__device__ __forceinline__ void red4(float* p, float a, float b, float c, float d) {
    asm volatile("red.global.add.v4.f32 [%0], {%1,%2,%3,%4};"
                 :: "l"(p), "f"(a), "f"(b), "f"(c), "f"(d) : "memory");
}
__device__ __forceinline__ void red2(float* p, float a, float b) {
    asm volatile("red.global.add.v2.f32 [%0], {%1,%2};"
                 :: "l"(p), "f"(a), "f"(b) : "memory");
}
__device__ __forceinline__ float leaky(float m) { return fmaxf(m, 0.2f * m); }
__device__ __forceinline__ void cpa16(__half* smem_dst, const __half* gsrc) {
    unsigned d = (unsigned)__cvta_generic_to_shared(smem_dst);
    asm volatile("cp.async.ca.shared.global [%0], [%1], 16;"
                 :: "r"(d), "l"(gsrc) : "memory");
}
__device__ __forceinline__ unsigned h2_bits(__half2 v) {
    return *reinterpret_cast<unsigned*>(&v);
}
__device__ __forceinline__ void mma16816(float& d0, float& d1, float& d2, float& d3,
                                         u32 a0, u32 a1, u32 a2, u32 a3,
                                         u32 b0, u32 b1) {
    asm volatile(
        "mma.sync.aligned.m16n8k16.row.col.f32.f16.f16.f32 "
        "{%0,%1,%2,%3}, {%4,%5,%6,%7}, {%8,%9}, {%0,%1,%2,%3};"
        : "+f"(d0), "+f"(d1), "+f"(d2), "+f"(d3)
        : "r"(a0), "r"(a1), "r"(a2), "r"(a3), "r"(b0), "r"(b1));
}

// ---------------------------------------------------------------------------
// Kernel 0: build transposed fp16 weight matrix Wt[96][16] = [We | Wg1]^T
// ---------------------------------------------------------------------------
__global__ void k_wcvt(const float* __restrict__ We, const float* __restrict__ Wg1) {
    int i = blockIdx.x * blockDim.x + threadIdx.x;
    if (i < 96 * 16) {
        int c = i >> 4, k = i & 15;
        float v = (c < 64) ? We[k * 64 + c] : Wg1[k * 32 + (c - 64)];
        g_Wt[i] = __float2half_rn(v);
    }
}

// ---------------------------------------------------------------------------
// Kernel 1: node transforms (fp16 out) + init accumulators + zero d_out.
// TWO-PASS weight staging: one 16KB Ws buffer reused for Wl then Wr
// -> smem 33KB -> ~7 blocks/SM (was 49KB / 4.6 blocks).
// ---------------------------------------------------------------------------
__global__ void __launch_bounds__(256) k_prep(
        const float* __restrict__ x,
        const float* __restrict__ Wl, const float* __restrict__ bl,
        const float* __restrict__ Wr, const float* __restrict__ br,
        float* __restrict__ out) {
    __shared__ __align__(16) float Ws[64 * 64];    // 16KB, reused per pass
    __shared__ __align__(16) float xs[64 * 64];    // 16KB
    int t = threadIdx.x;
    int nb = blockIdx.x * 64;

#pragma unroll
    for (int i = 0; i < 16; i++) {
        int idx = t + i * 256;
        int n = nb + (idx >> 6);
        bool ok = n < NN;
        xs[idx] = ok ? x[(size_t)n * 64 + (idx & 63)] : 0.f;
        if (ok) out[(size_t)n * 64 + (idx & 63)] = 0.f;
    }
    if (t < 64) {
        int n = nb + t;
        if (n < NN) {
            g_denom[n] = make_float4(0.f, 0.f, 0.f, 0.f);
            g_gate2[n] = make_float2(0.f, 0.f);
        }
    }

    int cg = t & 15, ng = t >> 4;       // 16 node-groups x 4 nodes; 64 cols
    int c0 = cg * 4;

#pragma unroll
    for (int pass = 0; pass < 2; pass++) {
        const float* W = pass ? Wr : Wl;
        const float* b = pass ? br : bl;
        __half* dsth   = pass ? g_xrh : g_xlh;

        __syncthreads();                // protect Ws reuse (and xs on pass 0)
#pragma unroll
        for (int i = 0; i < 16; i++)
            Ws[t + i * 256] = W[t + i * 256];
        __syncthreads();

        float4 bias = *(const float4*)&b[c0];
        u64 acc[4][2];
#pragma unroll
        for (int j = 0; j < 4; j++) {
            acc[j][0] = pack2(bias.x, bias.y);
            acc[j][1] = pack2(bias.z, bias.w);
        }

        for (int k4 = 0; k4 < 16; k4++) {
            float4 xv[4];
#pragma unroll
            for (int j = 0; j < 4; j++)
                xv[j] = *(const float4*)&xs[(ng * 4 + j) * 64 + k4 * 4];
#pragma unroll
            for (int kk = 0; kk < 4; kk++) {
                float4 wv = *(const float4*)&Ws[(k4 * 4 + kk) * 64 + c0];
                u64 w01 = pack2(wv.x, wv.y), w23 = pack2(wv.z, wv.w);
#pragma unroll
                for (int j = 0; j < 4; j++) {
                    float xsc = (kk == 0) ? xv[j].x : (kk == 1) ? xv[j].y
                              : (kk == 2) ? xv[j].z : xv[j].w;
                    u64 xx = pack2(xsc, xsc);
                    fma2(acc[j][0], xx, w01);
                    fma2(acc[j][1], xx, w23);
                }
            }
        }

#pragma unroll
        for (int j = 0; j < 4; j++) {
            int n = nb + ng * 4 + j;
            if (n < NN) {
                float o0, o1, o2, o3;
                unpack2(acc[j][0], o0, o1);
                unpack2(acc[j][1], o2, o3);
                uint2 p;
                p.x = h2_bits(__floats2half2_rn(o0, o1));
                p.y = h2_bits(__floats2half2_rn(o2, o3));
                *(uint2*)&dsth[(size_t)n * 64 + c0] = p;
            }
        }
    }
}

// ---------------------------------------------------------------------------
// Kernel 2 (fused edge pass, tensor-core matmuls, R13 + barrier restructure):
//   params staged via LDG+STS; the block-wide __syncthreads executes WHILE
//   the cp.async gathers are in flight; after the wait only __syncwarp.
// ---------------------------------------------------------------------------
#define ETPB 128
#define RST 72                              // halfs per staged xl/xr row
#define EAST 20                             // halfs per ea row (16 + 4 pad)

__global__ void __launch_bounds__(ETPB) k_edge(
        const int* __restrict__ ei, const float* __restrict__ eag,
        const float* __restrict__ att, const float* __restrict__ Wg2,
        const float* __restrict__ bg1, const float* __restrict__ bg2p,
        float* __restrict__ out) {
    __shared__ __align__(16) __half sXL[4][32 * RST];
    __shared__ __align__(16) __half sXR[4][32 * RST];   // meta reuses this later
    __shared__ __align__(16) __half sEA[4][32 * EAST];
    __shared__ __align__(16) __half sWt[96 * 16];
    __shared__ __align__(16) float  sAtt[64];
    __shared__ __align__(8)  float  sWg2[32];
    __shared__ __align__(8)  float  sBg1[32];

    int t = threadIdx.x, lane = t & 31, w = t >> 5;
    __half* XL = sXL[w];
    __half* XR = sXR[w];
    __half* EA = sEA[w];

    int e = blockIdx.x * ETPB + t;          // EE % ETPB == 0
    int src = ei[e];
    int tgt = ei[EE + e];

    // 1) issue per-warp xl/xr row gathers FIRST (cp.async, 4 rows/line each)
    int rlane = lane >> 3;
    int off8  = (lane & 7) * 8;
#pragma unroll
    for (int i = 0; i < 8; i++) {
        int r  = i * 4 + rlane;
        int s  = __shfl_sync(0xFFFFFFFFu, src, r);
        int tg = __shfl_sync(0xFFFFFFFFu, tgt, r);
        cpa16(&XL[r * RST + off8], g_xlh + (size_t)s  * 64 + off8);
        cpa16(&XR[r * RST + off8], g_xrh + (size_t)tg * 64 + off8);
    }
    asm volatile("cp.async.commit_group;" ::: "memory");

    // 2) stage params via LDG+STS (overlaps the gathers)
    {
        const uint4* wt4 = (const uint4*)g_Wt;     // 192 x 16B
        uint4* swt4 = (uint4*)sWt;
        for (int i = t; i < 192; i += ETPB) swt4[i] = wt4[i];
    }
    if (t < 64) sAtt[t] = att[t];
    if (t >= 64 && t < 96)  sWg2[t - 64] = Wg2[t - 64];
    if (t >= 96 && t < 128) sBg1[t - 96] = bg1[t - 96];

    // 3) coalesced eag load + fp16 transpose into EA[32][20] (own warp only)
    {
        const float4* eabase = (const float4*)eag
                             + (size_t)(blockIdx.x * ETPB + 32 * w) * 4;
#pragma unroll
        for (int i = 0; i < 4; i++) {
            int j = lane + 32 * i;
            float4 v = eabase[j];
            int ed = j >> 2, qq = j & 3;
            uint2 p;
            p.x = h2_bits(__floats2half2_rn(v.x, v.y));
            p.y = h2_bits(__floats2half2_rn(v.z, v.w));
            *(uint2*)&EA[ed * EAST + qq * 4] = p;
        }
    }
    float bg2v = bg2p[0];

    // 4) block barrier now (gathers still in flight), then per-warp wait only
    __syncthreads();
    asm volatile("cp.async.wait_group 0;" ::: "memory");
    __syncwarp();

    int gr = lane >> 2;
    int q  = lane & 3;

    u32 a0m0 = *(const u32*)&EA[gr * EAST + 2 * q];
    u32 a1m0 = *(const u32*)&EA[(gr + 8) * EAST + 2 * q];
    u32 a2m0 = *(const u32*)&EA[gr * EAST + 2 * q + 8];
    u32 a3m0 = *(const u32*)&EA[(gr + 8) * EAST + 2 * q + 8];
    u32 a0m1 = *(const u32*)&EA[(gr + 16) * EAST + 2 * q];
    u32 a1m1 = *(const u32*)&EA[(gr + 24) * EAST + 2 * q];
    u32 a2m1 = *(const u32*)&EA[(gr + 16) * EAST + 2 * q + 8];
    u32 a3m1 = *(const u32*)&EA[(gr + 24) * EAST + 2 * q + 8];

    float ap[4][4] = {};
    float gp[4]    = {0.f, 0.f, 0.f, 0.f};

#pragma unroll
    for (int nt = 0; nt < 12; nt++) {
        u32 b0 = *(const u32*)&sWt[(8 * nt + gr) * 16 + 2 * q];
        u32 b1 = *(const u32*)&sWt[(8 * nt + gr) * 16 + 2 * q + 8];

#pragma unroll
        for (int mt = 0; mt < 2; mt++) {
            float d0 = 0.f, d1 = 0.f, d2 = 0.f, d3 = 0.f;
            if (mt == 0) mma16816(d0, d1, d2, d3, a0m0, a1m0, a2m0, a3m0, b0, b1);
            else         mma16816(d0, d1, d2, d3, a0m1, a1m1, a2m1, a3m1, b0, b1);

            int r0 = gr + 16 * mt;
            if (nt < 8) {
                int col = 8 * nt + 2 * q;
                int h   = nt >> 1;
                float2 attv = *(const float2*)&sAtt[col];
                __half2 xl2 = *(const __half2*)&XL[r0 * RST + col];
                __half2 xr2 = *(const __half2*)&XR[r0 * RST + col];
                float2 f = __half22float2(__hadd2(xl2, xr2));
                float m0 = d0 + f.x, m1 = d1 + f.y;
                ap[2 * mt][h] += leaky(m0) * attv.x + leaky(m1) * attv.y;
                xl2 = *(const __half2*)&XL[(r0 + 8) * RST + col];
                xr2 = *(const __half2*)&XR[(r0 + 8) * RST + col];
                f = __half22float2(__hadd2(xl2, xr2));
                m0 = d2 + f.x; m1 = d3 + f.y;
                ap[2 * mt + 1][h] += leaky(m0) * attv.x + leaky(m1) * attv.y;
            } else {
                int hc = 8 * (nt - 8) + 2 * q;
                float2 b1v = *(const float2*)&sBg1[hc];
                float2 w2v = *(const float2*)&sWg2[hc];
                float h0 = d0 + b1v.x, h1 = d1 + b1v.y;
                gp[2 * mt]     += h0 * sigmoidf_(h0) * w2v.x +
                                  h1 * sigmoidf_(h1) * w2v.y;
                h0 = d2 + b1v.x; h1 = d3 + b1v.y;
                gp[2 * mt + 1] += h0 * sigmoidf_(h0) * w2v.x +
                                  h1 * sigmoidf_(h1) * w2v.y;
            }
        }
    }

#pragma unroll
    for (int s = 0; s < 4; s++) {
#pragma unroll
        for (int h = 0; h < 4; h++) {
            ap[s][h] += __shfl_xor_sync(0xFFFFFFFFu, ap[s][h], 1);
            ap[s][h] += __shfl_xor_sync(0xFFFFFFFFu, ap[s][h], 2);
        }
        gp[s] += __shfl_xor_sync(0xFFFFFFFFu, gp[s], 1);
        gp[s] += __shfl_xor_sync(0xFFFFFFFFu, gp[s], 2);
    }

    // lane q of each quad finalizes row r = gr + 8q
    int r = gr + 8 * q;
    float e0 = __expf(ap[q][0]);
    float e1 = __expf(ap[q][1]);
    float e2 = __expf(ap[q][2]);
    float e3 = __expf(ap[q][3]);
    float gate = sigmoidf_(gp[q] + bg2v);
    int tgt_r = __shfl_sync(0xFFFFFFFFu, tgt, r);

    __syncwarp();                            // XR reads done -> reuse as meta
    float* mw = (float*)XR;                  // meta [32][8] floats
    mw[r * 8 + 0] = e0; mw[r * 8 + 1] = e1;
    mw[r * 8 + 2] = e2; mw[r * 8 + 3] = e3;
    mw[r * 8 + 4] = __int_as_float(tgt_r);
    red4((float*)&g_denom[tgt_r], e0, e1, e2, e3);
    red2((float*)&g_gate2[tgt_r], gate, 1.f);
    __syncwarp();

    // phase C: messages from staged fp16 xl, cooperative red4 scatter
    int q15  = lane & 15;
    int rsel = lane >> 4;
    int h_c  = q15 >> 2;
#pragma unroll
    for (int i = 0; i < 16; i++) {
        int rr   = 2 * i + rsel;
        float a  = mw[rr * 8 + h_c];
        int tg   = __float_as_int(mw[rr * 8 + 4]);
        uint2 hv = *(const uint2*)&XL[rr * RST + q15 * 4];
        float2 f01 = __half22float2(*(const __half2*)&hv.x);
        float2 f23 = __half22float2(*(const __half2*)&hv.y);
        red4(out + (size_t)tg * 64 + q15 * 4,
             f01.x * a, f01.y * a, f23.x * a, f23.y * a);
    }
}

// ---------------------------------------------------------------------------
// Kernel 3: node epilogue — 16 threads/node, float4 lanes, global params.
// ---------------------------------------------------------------------------
__global__ void k_final(const float* __restrict__ x,
                        const float* __restrict__ conv_bias,
                        const float* __restrict__ gamma,
                        const float* __restrict__ beta,
                        float* __restrict__ out) {
    int gid = blockIdx.x * blockDim.x + threadIdx.x;
    int n = gid >> 4;
    int q = threadIdx.x & 15;
    int h = q >> 2;

    float2 gd = g_gate2[n];
    float mg = gd.x / fmaxf(gd.y, 1.f);
    float4 den4 = g_denom[n];
    float den = (h == 0) ? den4.x : (h == 1) ? den4.y : (h == 2) ? den4.z : den4.w;
    float inv = den > 0.f ? 1.f / den : 0.f;

    size_t idx = (size_t)n * 16 + q;
    float4 o  = ((const float4*)out)[idx];
    float4 cb = __ldg(&((const float4*)conv_bias)[q]);
    float4 v;
    v.x = (o.x * inv + cb.x) * mg;
    v.y = (o.y * inv + cb.y) * mg;
    v.z = (o.z * inv + cb.z) * mg;
    v.w = (o.w * inv + cb.w) * mg;

    float s  = v.x + v.y + v.z + v.w;
    float sq = v.x * v.x + v.y * v.y + v.z * v.z + v.w * v.w;
#pragma unroll
    for (int ofs = 1; ofs < 16; ofs <<= 1) {
        s  += __shfl_xor_sync(0xFFFFFFFFu, s,  ofs);
        sq += __shfl_xor_sync(0xFFFFFFFFu, sq, ofs);
    }
    float mu   = s * (1.f / 64.f);
    float var  = sq * (1.f / 64.f) - mu * mu;
    float rstd = rsqrtf(var + 1e-5f);

    float4 g  = __ldg(&((const float4*)gamma)[q]);
    float4 bt = __ldg(&((const float4*)beta)[q]);
    float4 xv = ((const float4*)x)[idx];
    float4 rr;
    float n0 = (v.x - mu) * rstd * g.x + bt.x;  n0 *= sigmoidf_(n0);  rr.x = n0 + xv.x;
    float n1 = (v.y - mu) * rstd * g.y + bt.y;  n1 *= sigmoidf_(n1);  rr.y = n1 + xv.y;
    float n2 = (v.z - mu) * rstd * g.z + bt.z;  n2 *= sigmoidf_(n2);  rr.z = n2 + xv.z;
    float n3 = (v.w - mu) * rstd * g.w + bt.w;  n3 *= sigmoidf_(n3);  rr.w = n3 + xv.w;
    ((float4*)out)[idx] = rr;
}

// ---------------------------------------------------------------------------
extern "C" void kernel_launch(void* const* d_in, const int* in_sizes, int n_in,
                              void* d_out, int out_size) {
    const float* x         = (const float*)d_in[0];
    const int*   ei        = (const int*)  d_in[1];
    const float* edge_attr = (const float*)d_in[2];
    const float* Wl        = (const float*)d_in[3];
    const float* bl        = (const float*)d_in[4];
    const float* Wr        = (const float*)d_in[5];
    const float* br        = (const float*)d_in[6];
    const float* We        = (const float*)d_in[7];
    const float* att       = (const float*)d_in[8];
    const float* conv_bias = (const float*)d_in[9];
    const float* Wg1       = (const float*)d_in[10];
    const float* bg1       = (const float*)d_in[11];
    const float* Wg2       = (const float*)d_in[12];
    const float* bg2       = (const float*)d_in[13];
    const float* gamma     = (const float*)d_in[14];
    const float* beta      = (const float*)d_in[15];
    float* out = (float*)d_out;

    k_wcvt <<<6, 256>>>(We, Wg1);
    k_prep <<<(NN + 63) / 64, 256>>>(x, Wl, bl, Wr, br, out);
    k_edge <<<EE / ETPB, ETPB>>>(ei, edge_attr, att, Wg2, bg1, bg2, out);
    k_final<<<NN * 16 / TPB, TPB>>>(x, conv_bias, gamma, beta, out);
}